// round 3
// baseline (speedup 1.0000x reference)
#include <cuda_runtime.h>
#include <cuda_bf16.h>
#include <cstdint>

#define VOCAB 50257
#define BATCH 512
#define SEQ   512

// Interleaved weight table: Wt[v] = (W[0][v], W[1][v]). One 32B sector
// serves both classes for a token -> halves L1tex wavefronts + L2 sectors.
__device__ float2 g_Wt[VOCAB];

__global__ void pack_w_kernel(const float* __restrict__ W) {
    int i = blockIdx.x * blockDim.x + threadIdx.x;
    if (i < VOCAB) {
        g_Wt[i] = make_float2(__ldg(W + i), __ldg(W + VOCAB + i));
    }
}

// One CTA per batch row. 256 threads, 2 tokens/thread via int2.
// Branch-free masked gathers so all LDGs are front-batched.
__global__ __launch_bounds__(256) void bow_gather_kernel(
    const int* __restrict__ ids,
    const float* __restrict__ bias,
    float* __restrict__ out)
{
    const int row = blockIdx.x;
    const int t   = threadIdx.x;   // 0..255

    const int2 v = reinterpret_cast<const int2*>(ids + row * SEQ)[t];

    // Unconditional gathers (ids are in [0, VOCAB)); mask pad-token 0.
    float2 w0 = g_Wt[v.x];
    float2 w1 = g_Wt[v.y];
    const float m0 = (v.x != 0) ? 1.0f : 0.0f;
    const float m1 = (v.y != 0) ? 1.0f : 0.0f;

    float s0 = fmaf(m0, w0.x, m1 * w1.x);
    float s1 = fmaf(m0, w0.y, m1 * w1.y);

    // Warp reduce
    #pragma unroll
    for (int o = 16; o > 0; o >>= 1) {
        s0 += __shfl_xor_sync(0xFFFFFFFFu, s0, o);
        s1 += __shfl_xor_sync(0xFFFFFFFFu, s1, o);
    }

    __shared__ float sm0[8], sm1[8];
    const int wid = t >> 5, lid = t & 31;
    if (lid == 0) { sm0[wid] = s0; sm1[wid] = s1; }
    __syncthreads();

    if (wid == 0 && lid < 8) {
        float r0 = sm0[lid];
        float r1 = sm1[lid];
        #pragma unroll
        for (int o = 4; o > 0; o >>= 1) {
            r0 += __shfl_xor_sync(0x000000FFu, r0, o);
            r1 += __shfl_xor_sync(0x000000FFu, r1, o);
        }
        if (lid == 0) {
            out[row * 2 + 0] = r0 + __ldg(bias + 0);
            out[row * 2 + 1] = r1 + __ldg(bias + 1);
        }
    }
}

extern "C" void kernel_launch(void* const* d_in, const int* in_sizes, int n_in,
                              void* d_out, int out_size) {
    const int*   ids  = (const int*)d_in[0];    // [512, 512] int32
    const float* W    = (const float*)d_in[1];  // [2, 50257] float32
    const float* bias = (const float*)d_in[2];  // [2] float32
    float* out = (float*)d_out;                 // [512, 2] float32

    pack_w_kernel<<<(VOCAB + 255) / 256, 256>>>(W);
    bow_gather_kernel<<<BATCH, 256>>>(ids, bias, out);
}